// round 9
// baseline (speedup 1.0000x reference)
#include <cuda_runtime.h>
#include <cstddef>
#include <cstdint>

// Problem constants
#define B_   4
#define TQ_  512
#define TP_  512
#define D_   256

// ---------------------------------------------------------------------------
// Scratch (static device globals)
// ---------------------------------------------------------------------------
__device__ float g_partP[(size_t)4 * B_ * TQ_ * D_];  // proj partials, slice (s*2+t)
__device__ float g_sc[(size_t)B_ * TP_ * TQ_];        // exp(scores) [B,Tp,Tq]
__device__ float g_cpart[B_ * 8 * TQ_];               // per-p-tile column partials
__device__ float g_partO[(size_t)16 * TP_ * D_];      // out partials, slice (s*4+b)

// ---------------------------------------------------------------------------
// Streams/events for the batch-pipelined schedule (created once at load;
// stream/event creation does not allocate tracked device memory).
// ---------------------------------------------------------------------------
struct PipeRes {
    cudaStream_t sP, sO, sE[4];
    cudaEvent_t evRoot, evP[4], evE[4], evD[6];
    PipeRes() {
        cudaStreamCreateWithFlags(&sP, cudaStreamNonBlocking);
        cudaStreamCreateWithFlags(&sO, cudaStreamNonBlocking);
        for (int i = 0; i < 4; i++)
            cudaStreamCreateWithFlags(&sE[i], cudaStreamNonBlocking);
        cudaEventCreateWithFlags(&evRoot, cudaEventDisableTiming);
        for (int i = 0; i < 4; i++) {
            cudaEventCreateWithFlags(&evP[i], cudaEventDisableTiming);
            cudaEventCreateWithFlags(&evE[i], cudaEventDisableTiming);
        }
        for (int i = 0; i < 6; i++)
            cudaEventCreateWithFlags(&evD[i], cudaEventDisableTiming);
    }
};
static PipeRes g_pipe;

// ---------------------------------------------------------------------------
// fp32 HW tanh (1 MUFU op).
// ---------------------------------------------------------------------------
__device__ __forceinline__ float ftanh(float x) {
    float r;
    asm("tanh.approx.f32 %0, %1;" : "=f"(r) : "f"(x));
    return r;
}

__device__ __forceinline__ uint32_t f2tf32(float x) {
    uint32_t r;
    asm("cvt.rna.tf32.f32 %0, %1;" : "=r"(r) : "f"(x));
    return r;
}

// ---------------------------------------------------------------------------
// tf32 tensor-core GEMM slice (proven R6/R8 geometry).
// Block tile 64x64, BK=32, 256 threads = 8 warps (2m x 4n),
// warp tile 32x16: 2 m-frags x 2 n-frags of m16n8k8.
// C[M,N] (partial) = A[M, kbeg:kend] * B[kbeg:kend, N], both row-major.
// If SCALE, A column k is scaled by cs[k] at load (cs may be smem).
// ---------------------------------------------------------------------------
template <bool SCALE>
__device__ __forceinline__ void tf32_gemm_64x64(const float* __restrict__ A,
                                                const float* __restrict__ B,
                                                float* __restrict__ C,
                                                const float* cs,
                                                int N, int K, int kbeg, int kend,
                                                int m0, int n0) {
    __shared__ uint32_t As[64][36];  // [m][k]
    __shared__ uint32_t Bs[32][72];  // [k][n]

    const int tid = threadIdx.x;
    const int lane = tid & 31;
    const int w = tid >> 5;
    const int wm = (w >> 2) * 32;
    const int wn = (w & 3) * 16;
    const int frow = lane >> 2;
    const int fcol = lane & 3;

    float c[2][2][4];
#pragma unroll
    for (int mi = 0; mi < 2; mi++)
#pragma unroll
        for (int ni = 0; ni < 2; ni++)
#pragma unroll
            for (int k = 0; k < 4; k++) c[mi][ni][k] = 0.0f;

    float4 ra[2], rb[2];
    auto loadG = [&](int k0) {
#pragma unroll
        for (int s = 0; s < 2; s++) {
            int id = tid + s * 256;
            int r = id >> 3, cc = (id & 7) * 4;
            ra[s] = *(const float4*)&A[(size_t)(m0 + r) * K + k0 + cc];
            if (SCALE) {
                float4 sc = *(const float4*)&cs[k0 + cc];
                ra[s].x *= sc.x; ra[s].y *= sc.y;
                ra[s].z *= sc.z; ra[s].w *= sc.w;
            }
        }
#pragma unroll
        for (int s = 0; s < 2; s++) {
            int id = tid + s * 256;
            int r = id >> 4, cc = (id & 15) * 4;
            rb[s] = *(const float4*)&B[(size_t)(k0 + r) * N + n0 + cc];
        }
    };
    auto storeS = [&]() {
#pragma unroll
        for (int s = 0; s < 2; s++) {
            int id = tid + s * 256;
            int r = id >> 3, cc = (id & 7) * 4;
            As[r][cc + 0] = f2tf32(ra[s].x);
            As[r][cc + 1] = f2tf32(ra[s].y);
            As[r][cc + 2] = f2tf32(ra[s].z);
            As[r][cc + 3] = f2tf32(ra[s].w);
        }
#pragma unroll
        for (int s = 0; s < 2; s++) {
            int id = tid + s * 256;
            int r = id >> 4, cc = (id & 15) * 4;
            Bs[r][cc + 0] = f2tf32(rb[s].x);
            Bs[r][cc + 1] = f2tf32(rb[s].y);
            Bs[r][cc + 2] = f2tf32(rb[s].z);
            Bs[r][cc + 3] = f2tf32(rb[s].w);
        }
    };

    loadG(kbeg);
    for (int k0 = kbeg; k0 < kend; k0 += 32) {
        storeS();
        __syncthreads();
        if (k0 + 32 < kend) loadG(k0 + 32);
#pragma unroll
        for (int ks = 0; ks < 4; ks++) {
            const int kk = ks * 8;
            uint32_t a[2][4], bfr[2][2];
#pragma unroll
            for (int mi = 0; mi < 2; mi++) {
                a[mi][0] = As[wm + mi * 16 + frow][kk + fcol];
                a[mi][1] = As[wm + mi * 16 + frow + 8][kk + fcol];
                a[mi][2] = As[wm + mi * 16 + frow][kk + fcol + 4];
                a[mi][3] = As[wm + mi * 16 + frow + 8][kk + fcol + 4];
            }
#pragma unroll
            for (int ni = 0; ni < 2; ni++) {
                bfr[ni][0] = Bs[kk + fcol][wn + ni * 8 + frow];
                bfr[ni][1] = Bs[kk + fcol + 4][wn + ni * 8 + frow];
            }
#pragma unroll
            for (int mi = 0; mi < 2; mi++)
#pragma unroll
                for (int ni = 0; ni < 2; ni++)
                    asm volatile(
                        "mma.sync.aligned.m16n8k8.row.col.f32.tf32.tf32.f32 "
                        "{%0,%1,%2,%3},{%4,%5,%6,%7},{%8,%9},{%0,%1,%2,%3};"
                        : "+f"(c[mi][ni][0]), "+f"(c[mi][ni][1]),
                          "+f"(c[mi][ni][2]), "+f"(c[mi][ni][3])
                        : "r"(a[mi][0]), "r"(a[mi][1]), "r"(a[mi][2]),
                          "r"(a[mi][3]), "r"(bfr[ni][0]), "r"(bfr[ni][1]));
        }
        __syncthreads();
    }

#pragma unroll
    for (int mi = 0; mi < 2; mi++)
#pragma unroll
        for (int ni = 0; ni < 2; ni++) {
            int rr = m0 + wm + mi * 16 + frow;
            int cc = n0 + wn + ni * 8 + fcol * 2;
            *(float2*)&C[(size_t)rr * N + cc] =
                make_float2(c[mi][ni][0], c[mi][ni][1]);
            *(float2*)&C[(size_t)(rr + 8) * N + cc] =
                make_float2(c[mi][ni][2], c[mi][ni][3]);
        }
}

// ---------------------------------------------------------------------------
// Kernel 1: per-batch projections (tf32 TC), split-K=2.  z = t + 2*s.
//   partP[s*2+t][rows of batch b] = (t?p:q)_b[:, ks:+128] @ (t?W1:W0)[ks:+128,:]
// grid (4, 8, 4) = 128 blocks.  NO reduce kernel: energy sums the two
// split partials inline.
// ---------------------------------------------------------------------------
__global__ __launch_bounds__(256) void proj_kernel(const float* __restrict__ q,
                                                   const float* __restrict__ p,
                                                   const float* __restrict__ W0,
                                                   const float* __restrict__ W1,
                                                   int b) {
    const int t = blockIdx.z & 1;
    const int s = blockIdx.z >> 1;
    const size_t boff = (size_t)b * TQ_ * D_;
    const float* A = (t ? p : q) + boff;
    const float* Bw = t ? W1 : W0;
    float* C = g_partP + (size_t)(s * 2 + t) * (B_ * TQ_ * D_) + boff;
    tf32_gemm_64x64<false>(A, Bw, C, nullptr, D_, D_,
                           s * 128, s * 128 + 128,
                           blockIdx.y * 64, blockIdx.x * 64);
}

// ---------------------------------------------------------------------------
// Kernel 2: per-batch energies -> exp(score) + column partials.
// Sums the two proj split-K partials inline while loading tiles (MUFU-bound,
// so the extra L2 reads and FADDs are free).
// fp32 MUFU.TANH, 64x64 tile, 4x4 micro -- at the MUFU throughput floor.
// grid (8, 8) = 64 blocks per batch.
// ---------------------------------------------------------------------------
__global__ __launch_bounds__(256) void energy_kernel(const float* __restrict__ vc,
                                                     int b) {
    __shared__ float sp[64][33];
    __shared__ float sq[64][33];
    __shared__ float sv[32];
    __shared__ float colred[16][64];

    const int p0 = blockIdx.y * 64;
    const int q0 = blockIdx.x * 64;
    const int tid = threadIdx.x;
    const int tx = tid & 15;
    const int ty = tid >> 4;

    constexpr size_t NFT = (size_t)B_ * TQ_ * D_;
    // t=0 -> pq, t=1 -> pp ; s=0 at slice offset 0/1, s=1 at 2/3
    const float* pq_a = g_partP + 0 * NFT + ((size_t)b * TQ_ + q0) * D_;
    const float* pq_b = g_partP + 2 * NFT + ((size_t)b * TQ_ + q0) * D_;
    const float* pp_a = g_partP + 1 * NFT + ((size_t)b * TP_ + p0) * D_;
    const float* pp_b = g_partP + 3 * NFT + ((size_t)b * TP_ + p0) * D_;

    float acc[4][4];
#pragma unroll
    for (int i = 0; i < 4; i++)
#pragma unroll
        for (int j = 0; j < 4; j++) acc[i][j] = 0.0f;

    for (int d0 = 0; d0 < D_; d0 += 32) {
        if (tid < 32) sv[tid] = vc[d0 + tid];
#pragma unroll
        for (int s = 0; s < 2; s++) {
            int id = tid + s * 256;
            int r = id >> 3, cc = (id & 7) * 4;
            size_t off = (size_t)r * D_ + d0 + cc;
            float4 Pa = *(const float4*)&pp_a[off];
            float4 Pb = *(const float4*)&pp_b[off];
            float4 Qa = *(const float4*)&pq_a[off];
            float4 Qb = *(const float4*)&pq_b[off];
            sp[r][cc + 0] = Pa.x + Pb.x; sp[r][cc + 1] = Pa.y + Pb.y;
            sp[r][cc + 2] = Pa.z + Pb.z; sp[r][cc + 3] = Pa.w + Pb.w;
            sq[r][cc + 0] = Qa.x + Qb.x; sq[r][cc + 1] = Qa.y + Qb.y;
            sq[r][cc + 2] = Qa.z + Qb.z; sq[r][cc + 3] = Qa.w + Qb.w;
        }
        __syncthreads();

#pragma unroll 8
        for (int d = 0; d < 32; d++) {
            float v = sv[d];
            float a[4], bb[4];
#pragma unroll
            for (int i = 0; i < 4; i++) a[i] = sp[ty * 4 + i][d];
#pragma unroll
            for (int j = 0; j < 4; j++) bb[j] = sq[tx * 4 + j][d];
#pragma unroll
            for (int i = 0; i < 4; i++)
#pragma unroll
                for (int j = 0; j < 4; j++)
                    acc[i][j] = fmaf(v, ftanh(a[i] + bb[j]), acc[i][j]);
        }
        __syncthreads();
    }

    float colp[4] = {0.f, 0.f, 0.f, 0.f};
#pragma unroll
    for (int i = 0; i < 4; i++) {
        float4 o;
        o.x = __expf(acc[i][0]);
        o.y = __expf(acc[i][1]);
        o.z = __expf(acc[i][2]);
        o.w = __expf(acc[i][3]);
        colp[0] += o.x; colp[1] += o.y; colp[2] += o.z; colp[3] += o.w;
        *(float4*)&g_sc[((size_t)b * TP_ + p0 + ty * 4 + i) * TQ_ + q0 + tx * 4] = o;
    }
    *(float4*)&colred[ty][tx * 4] =
        make_float4(colp[0], colp[1], colp[2], colp[3]);
    __syncthreads();
    if (tid < 64) {
        float s = colred[0][tid];
#pragma unroll
        for (int t = 1; t < 16; t++) s += colred[t][tid];
        g_cpart[(b * 8 + blockIdx.y) * TQ_ + q0 + tid] = s;
    }
}

// ---------------------------------------------------------------------------
// Kernel 3: per-batch out GEMM (tf32 TC), split-K=4, in-block column-sum
// inverse + normalize fused into A load.  grid (4, 8, 4) = 128 blocks.
// ---------------------------------------------------------------------------
__global__ __launch_bounds__(256) void out_gemm_kernel(const float* __restrict__ qin,
                                                       int b) {
    __shared__ __align__(16) float sinv[128];

    const int s = blockIdx.z;
    const int kbeg = s * 128;
    const int tid = threadIdx.x;

    if (tid < 128) {
        const int qq = kbeg + tid;
        float sum = 0.f;
#pragma unroll
        for (int t = 0; t < 8; t++) sum += g_cpart[(b * 8 + t) * TQ_ + qq];
        sinv[tid] = __fdividef(1.0f, sum);
    }
    __syncthreads();

    float* C = g_partO + (size_t)(s * 4 + b) * (TP_ * D_);
    tf32_gemm_64x64<true>(g_sc + (size_t)b * TP_ * TQ_,
                          qin + (size_t)b * TQ_ * D_, C,
                          sinv - kbeg, D_, TQ_,
                          kbeg, kbeg + 128,
                          blockIdx.y * 64, blockIdx.x * 64);
}

// Per-batch reduce of out partials.  grid (128) x 256.
__global__ __launch_bounds__(256) void out_reduce_kernel(float* __restrict__ out,
                                                         int b) {
    const int j = blockIdx.x * 256 + threadIdx.x;  // float4 idx within batch
    constexpr int NB4 = (TP_ * D_) / 4;
    float4 r = make_float4(0.f, 0.f, 0.f, 0.f);
#pragma unroll
    for (int s = 0; s < 4; s++) {
        float4 v = *((const float4*)g_partO + (size_t)(s * 4 + b) * NB4 + j);
        r.x += v.x; r.y += v.y; r.z += v.z; r.w += v.w;
    }
    *((float4*)out + (size_t)b * NB4 + j) = r;
}

// ---------------------------------------------------------------------------
// Launch: batch-pipelined across streams.
//   sP:   proj(0) proj(1) proj(2) proj(3)
//   sE_b: wait proj(b) -> energy(b)
//   sO:   wait energy(b) -> out_gemm(b) -> out_reduce(b)   (b = 0..3)
// The GEMMs (tensor pipe) hide under the MUFU-bound energy backbone.
// ---------------------------------------------------------------------------
extern "C" void kernel_launch(void* const* d_in, const int* in_sizes, int n_in,
                              void* d_out, int out_size) {
    const float* q = (const float*)d_in[0];   // [B,Tq,D]
    const float* p = (const float*)d_in[1];   // [B,Tp,D]
    const float* W0 = (const float*)d_in[2];  // [D,D]
    const float* W1 = (const float*)d_in[3];  // [D,D]
    const float* vc = (const float*)d_in[4];  // [D,1]
    float* out = (float*)d_out;               // [B,Tp,D]

    PipeRes& S = g_pipe;

    // Fork all side streams from the (capture-origin) null stream.
    cudaEventRecord(S.evRoot, 0);
    cudaStreamWaitEvent(S.sP, S.evRoot, 0);
    cudaStreamWaitEvent(S.sO, S.evRoot, 0);
    for (int b = 0; b < 4; b++) cudaStreamWaitEvent(S.sE[b], S.evRoot, 0);

    dim3 gProj(D_ / 64, TQ_ / 64, 4);
    dim3 gEner(TQ_ / 64, TP_ / 64);
    dim3 gOut(D_ / 64, TP_ / 64, 4);

    for (int b = 0; b < 4; b++) {
        proj_kernel<<<gProj, 256, 0, S.sP>>>(q, p, W0, W1, b);
        cudaEventRecord(S.evP[b], S.sP);
    }
    for (int b = 0; b < 4; b++) {
        cudaStreamWaitEvent(S.sE[b], S.evP[b], 0);
        energy_kernel<<<gEner, 256, 0, S.sE[b]>>>(vc, b);
        cudaEventRecord(S.evE[b], S.sE[b]);
    }
    for (int b = 0; b < 4; b++) {
        cudaStreamWaitEvent(S.sO, S.evE[b], 0);
        out_gemm_kernel<<<gOut, 256, 0, S.sO>>>(q, b);
        out_reduce_kernel<<<128, 256, 0, S.sO>>>(out, b);
    }

    // Join everything back into the null stream.
    cudaEventRecord(S.evD[0], S.sP);
    cudaEventRecord(S.evD[1], S.sO);
    for (int b = 0; b < 4; b++) cudaEventRecord(S.evD[2 + b], S.sE[b]);
    for (int i = 0; i < 6; i++) cudaStreamWaitEvent(0, S.evD[i], 0);
}